// round 11
// baseline (speedup 1.0000x reference)
#include <cuda_runtime.h>
#include <cuda_bf16.h>
#include <cstdint>
#include <cstddef>

#define NN   8192
#define NWRD 256
#define NDC  64     // double-chunks of K=128

__device__ unsigned      g_bits[NN * NWRD];  // 8 MB adjacency bitmask
__device__ float         g_dinv[NN];
__device__ __nv_bfloat16 g_sbt[8 * NN];      // rows 0-3: hi(dinv_j*s_j), 4-7: lo
__device__ float         g_yf[64 * NN];      // f32 y' = dinv_j*(h1@W2), [e][j]
__device__ unsigned      g_amax[64];         // per-e max |y'| (as uint bits)
__device__ signed char   g_ys[128 * NN];     // rows 0-63: h(e), 64-127: l(e)

// ---------------- helpers ----------------
__device__ __forceinline__ uint32_t s2u(const void* p) {
    uint32_t a;
    asm("{ .reg .u64 t; cvta.to.shared.u64 t, %1; cvt.u32.u64 %0, t; }" : "=r"(a) : "l"(p));
    return a;
}
__device__ __forceinline__ uint32_t swz(uint32_t b) { return b ^ ((b >> 3) & 0x70); }
__device__ __forceinline__ void cpa16(uint32_t s, const void* g) {
    asm volatile("cp.async.cg.shared.global [%0], [%1], 16;" :: "r"(s), "l"(g) : "memory");
}
#define CP_COMMIT() asm volatile("cp.async.commit_group;" ::: "memory")
#define CP_WAIT(n)  asm volatile("cp.async.wait_group %0;" :: "n"(n) : "memory")

__device__ __forceinline__ uint4 lds128(uint32_t a) {
    uint4 v;
    asm("ld.shared.v4.b32 {%0,%1,%2,%3}, [%4];"
        : "=r"(v.x), "=r"(v.y), "=r"(v.z), "=r"(v.w) : "r"(a));
    return v;
}
__device__ __forceinline__ void ldmx4(uint32_t& r0, uint32_t& r1, uint32_t& r2, uint32_t& r3,
                                      uint32_t a) {
    asm volatile("ldmatrix.sync.aligned.m8n8.x4.shared.b16 {%0,%1,%2,%3}, [%4];"
                 : "=r"(r0), "=r"(r1), "=r"(r2), "=r"(r3) : "r"(a));
}
__device__ __forceinline__ void ldmx2(uint32_t& r0, uint32_t& r1, uint32_t a) {
    asm volatile("ldmatrix.sync.aligned.m8n8.x2.shared.b16 {%0,%1}, [%2];"
                 : "=r"(r0), "=r"(r1) : "r"(a));
}
__device__ __forceinline__ uint32_t lutbf(uint32_t p) {
    return ((p & 1u) ? 0x3F80u : 0u) | ((p & 2u) ? 0x3F800000u : 0u);
}
// expand 4 mask bits -> 4 bytes of 0/1 (s8)
__device__ __forceinline__ uint32_t exp4(uint32_t p) {
    return (p * 0x00204081u) & 0x01010101u;
}
__device__ __forceinline__ void mma16816(float* c, uint32_t a0, uint32_t a1, uint32_t a2,
                                         uint32_t a3, uint32_t b0, uint32_t b1) {
    asm volatile("mma.sync.aligned.m16n8k16.row.col.f32.bf16.bf16.f32 "
                 "{%0,%1,%2,%3}, {%4,%5,%6,%7}, {%8,%9}, {%0,%1,%2,%3};"
                 : "+f"(c[0]), "+f"(c[1]), "+f"(c[2]), "+f"(c[3])
                 : "r"(a0), "r"(a1), "r"(a2), "r"(a3), "r"(b0), "r"(b1));
}
__device__ __forceinline__ void mmas8(int* c, uint32_t a0, uint32_t a1, uint32_t a2,
                                      uint32_t a3, uint32_t b0, uint32_t b1) {
    asm volatile("mma.sync.aligned.m16n8k32.row.col.s32.s8.s8.s32 "
                 "{%0,%1,%2,%3}, {%4,%5,%6,%7}, {%8,%9}, {%0,%1,%2,%3};"
                 : "+r"(c[0]), "+r"(c[1]), "+r"(c[2]), "+r"(c[3])
                 : "r"(a0), "r"(a1), "r"(a2), "r"(a3), "r"(b0), "r"(b1));
}
// decode 4 bf16 A regs (one kk step) from two 64-bit row-words (kG1 path)
__device__ __forceinline__ void decA(uint2 wg, uint2 wg8, int kk, int tq,
                                     uint32_t& a0, uint32_t& a1, uint32_t& a2, uint32_t& a3) {
    const uint32_t w0 = (kk < 2) ? wg.x : wg.y;
    const uint32_t w1 = (kk < 2) ? wg8.x : wg8.y;
    const int sh = ((kk & 1) << 4) + (tq << 1);
    a0 = lutbf((w0 >> sh) & 3u);
    a1 = lutbf((w1 >> sh) & 3u);
    a2 = lutbf((w0 >> (sh + 8)) & 3u);
    a3 = lutbf((w1 >> (sh + 8)) & 3u);
}

// ============================================================
// kA: distances -> f32 mask + bitmask + dinv + s' hi/lo; 4 rows per pos-load
// ============================================================
__global__ void __launch_bounds__(256) kA(const float4* __restrict__ st, float* __restrict__ omask) {
    extern __shared__ __align__(16) char smemA[];
    float2* spos = (float2*)smemA;
    int*    sdeg = (int*)(spos + NN);
    const int t = threadIdx.x, lane = t & 31;

    if (blockIdx.x == 0 && t < 64) g_amax[t] = 0u;   // reset per launch

    for (int j = t; j < NN; j += 256) { float4 s = st[j]; spos[j] = make_float2(s.x, s.y); }
    if (t < 16) sdeg[t] = 0;
    __syncthreads();

    const int row0 = blockIdx.x << 4;
    const float4* sp4 = (const float4*)spos;

    for (int rq = 0; rq < 4; ++rq) {
        const int ib = row0 + (rq << 2);
        float xr[4], yr[4];
#pragma unroll
        for (int q = 0; q < 4; ++q) { xr[q] = spos[ib + q].x; yr[q] = spos[ib + q].y; }
        int cnt[4] = {0, 0, 0, 0};
#pragma unroll
        for (int c = 0; c < 8; ++c) {
            const int j = (c << 10) + (t << 2);
            float4 p01 = sp4[j >> 1], p23 = sp4[(j >> 1) + 1];
#pragma unroll
            for (int q = 0; q < 4; ++q) {
                float dx0 = xr[q] - p01.x, dy0 = yr[q] - p01.y;
                float dx1 = xr[q] - p01.z, dy1 = yr[q] - p01.w;
                float dx2 = xr[q] - p23.x, dy2 = yr[q] - p23.y;
                float dx3 = xr[q] - p23.z, dy3 = yr[q] - p23.w;
                unsigned m0 = (dx0 * dx0 + dy0 * dy0 <= 1.0f);
                unsigned m1 = (dx1 * dx1 + dy1 * dy1 <= 1.0f);
                unsigned m2 = (dx2 * dx2 + dy2 * dy2 <= 1.0f);
                unsigned m3 = (dx3 * dx3 + dy3 * dy3 <= 1.0f);
                float4 mf = make_float4(m0 ? 1.f : 0.f, m1 ? 1.f : 0.f,
                                        m2 ? 1.f : 0.f, m3 ? 1.f : 0.f);
                *reinterpret_cast<float4*>(omask + (size_t)(ib + q) * NN + j) = mf;
                unsigned nib = m0 | (m1 << 1) | (m2 << 2) | (m3 << 3);
                cnt[q] += (int)(m0 + m1 + m2 + m3);
                unsigned v = nib << ((lane & 7) * 4);
                v |= __shfl_xor_sync(0xffffffffu, v, 1);
                v |= __shfl_xor_sync(0xffffffffu, v, 2);
                v |= __shfl_xor_sync(0xffffffffu, v, 4);
                if ((lane & 7) == 0) {
                    const int jb = (c << 10) + ((t >> 5) << 7);
                    g_bits[(ib + q) * NWRD + (jb >> 5) + (lane >> 3)] = v;
                }
            }
        }
#pragma unroll
        for (int q = 0; q < 4; ++q) {
#pragma unroll
            for (int o = 16; o; o >>= 1) cnt[q] += __shfl_xor_sync(0xffffffffu, cnt[q], o);
            if (lane == 0) atomicAdd(&sdeg[(rq << 2) + q], cnt[q]);
        }
    }
    __syncthreads();

    if (t < 16) {
        const int i = row0 + t;
        const float dinv = rsqrtf((float)sdeg[t]);
        g_dinv[i] = dinv;
        float4 s = st[i];
        float v[4] = { dinv * s.x, dinv * s.y, dinv * s.z, dinv * s.w };
#pragma unroll
        for (int d = 0; d < 4; ++d) {
            __nv_bfloat16 hi = __float2bfloat16(v[d]);
            g_sbt[d * NN + i] = hi;
            g_sbt[(4 + d) * NN + i] = __float2bfloat16(v[d] - __bfloat162float(hi));
        }
    }
}

// ---------------- chunk loaders ----------------
// kG1 (256 thr): mask 1KB + B 2KB (bf16)
__device__ __forceinline__ void ldch1(int m0, int dc, uint32_t sM, uint32_t sB, int t) {
    if (t < 128) {
        int sub = t >> 6, rem = t & 63, row = rem >> 3, seg = rem & 7;
        cpa16(sB + sub * 1024 + swz(row * 128 + seg * 16),
              g_sbt + (size_t)row * NN + dc * 128 + sub * 64 + seg * 8);
    } else if (t < 192) {
        int row = t - 128;
        cpa16(sM + row * 16, g_bits + (size_t)(m0 + row) * NWRD + dc * 4);
    }
}
// kG2 (512 thr): mask 1KB + B 16KB (s8, 128 rows x 128B)
__device__ __forceinline__ void ldch2(int m0, int dc, uint32_t sM, uint32_t sB, int t) {
    if (t < 64) cpa16(sM + t * 16, g_bits + (size_t)(m0 + t) * NWRD + dc * 4);
#pragma unroll
    for (int p = 0; p < 2; ++p) {
        int q = t + (p << 9);
        int row = q >> 3, seg = q & 7;
        cpa16(sB + swz(row * 128 + seg * 16),
              g_ys + (size_t)row * NN + dc * 128 + seg * 16);
    }
}

// ============================================================
// kG1: C[64x8] = A_tile @ [s'hi|s'lo]; split-K across warp halves; fused MLP.
// epilogue now emits f32 y' + per-e amax.
// smem: mask 3x1KB @0, B 3x2KB @3072, w1 @9216, b1 @10240, w2 @10496,
//       agg @26880 (2KB), smax @28928 (256B)
// ============================================================
__global__ void __launch_bounds__(256) kG1(const float* __restrict__ W1,
                                           const float* __restrict__ b1,
                                           const float* __restrict__ W2) {
    extern __shared__ __align__(16) char sm[];
    const uint32_t sb = s2u(sm);
    const int t = threadIdx.x, lane = t & 31, wid = t >> 5;
    const int g = lane >> 2, tq = lane & 3;
    const int h = wid >> 2, wr = wid & 3;
    const int m0 = blockIdx.x << 6;

    float*    w1s  = (float*)(sm + 9216);
    float*    b1s  = (float*)(sm + 10240);
    float*    w2s  = (float*)(sm + 10496);
    float*    agg  = (float*)(sm + 26880);   // [2][64][4]
    unsigned* smax = (unsigned*)(sm + 28928);

    if (t < 256) w1s[t] = W1[t];
    if (t < 64)  { b1s[t] = b1[t]; smax[t] = 0u; }
    for (int k = t; k < 4096; k += 256) w2s[k] = W2[k];

    const uint32_t MS = sb, BS = sb + 3072;
    const uint32_t lmbase = (lane & 7) * 128 + ((lane >> 3) & 1) * 16;

    float acc[4] = {0.f, 0.f, 0.f, 0.f};

#pragma unroll
    for (int s = 0; s < 2; ++s) { ldch1(m0, s, MS + s * 1024, BS + s * 2048, t); CP_COMMIT(); }

    for (int dc = 0; dc < NDC; ++dc) {
        const int s = dc % 3;
        CP_WAIT(1);
        __syncthreads();
        if (dc + 2 < NDC)
            ldch1(m0, dc + 2, MS + ((dc + 2) % 3) * 1024, BS + ((dc + 2) % 3) * 2048, t);
        CP_COMMIT();
        const uint32_t mS = MS + s * 1024;
        const uint32_t bsub = BS + s * 2048 + h * 1024;
        uint4 w0 = lds128(mS + (wr * 16 + g) * 16);
        uint4 w8 = lds128(mS + (wr * 16 + g + 8) * 16);
        uint2 wg  = h ? make_uint2(w0.z, w0.w) : make_uint2(w0.x, w0.y);
        uint2 wg8 = h ? make_uint2(w8.z, w8.w) : make_uint2(w8.x, w8.y);
#pragma unroll
        for (int kk = 0; kk < 4; ++kk) {
            uint32_t a0, a1, a2, a3, b0, b1r;
            decA(wg, wg8, kk, tq, a0, a1, a2, a3);
            ldmx2(b0, b1r, bsub + swz(lmbase + kk * 32));
            mma16816(acc, a0, a1, a2, a3, b0, b1r);
        }
    }
    CP_WAIT(0);

    {
        float s0 = acc[0] + __shfl_xor_sync(0xffffffffu, acc[0], 2);
        float s1 = acc[1] + __shfl_xor_sync(0xffffffffu, acc[1], 2);
        float s2 = acc[2] + __shfl_xor_sync(0xffffffffu, acc[2], 2);
        float s3 = acc[3] + __shfl_xor_sync(0xffffffffu, acc[3], 2);
        if (tq < 2) {
            const int row = wr * 16 + g;
            float* ag = agg + h * 256;
            ag[row * 4 + 2 * tq] = s0;
            ag[row * 4 + 2 * tq + 1] = s1;
            ag[(row + 8) * 4 + 2 * tq] = s2;
            ag[(row + 8) * 4 + 2 * tq + 1] = s3;
        }
    }
    __syncthreads();

    {
        const int r = t & 63, q = t >> 6, i = m0 + r;
        const float dinv = g_dinv[i];
        const float a0 = dinv * (agg[r * 4 + 0] + agg[256 + r * 4 + 0]);
        const float a1 = dinv * (agg[r * 4 + 1] + agg[256 + r * 4 + 1]);
        const float a2 = dinv * (agg[r * 4 + 2] + agg[256 + r * 4 + 2]);
        const float a3 = dinv * (agg[r * 4 + 3] + agg[256 + r * 4 + 3]);
        float hh[64];
#pragma unroll
        for (int k = 0; k < 64; ++k)
            hh[k] = fmaxf(b1s[k] + a0 * w1s[k] + a1 * w1s[64 + k]
                        + a2 * w1s[128 + k] + a3 * w1s[192 + k], 0.f);
        float y[16];
#pragma unroll
        for (int v = 0; v < 16; ++v) y[v] = 0.f;
        for (int k = 0; k < 64; ++k) {
            const float hk = hh[k];
            const float4* w4 = (const float4*)(w2s + k * 64 + q * 16);
#pragma unroll
            for (int v = 0; v < 4; ++v) {
                float4 w = w4[v];
                y[4 * v + 0] += hk * w.x;
                y[4 * v + 1] += hk * w.y;
                y[4 * v + 2] += hk * w.z;
                y[4 * v + 3] += hk * w.w;
            }
        }
#pragma unroll
        for (int v = 0; v < 16; ++v) {
            const int e = q * 16 + v;
            const float yy = dinv * y[v];
            g_yf[e * NN + i] = yy;
            atomicMax(&smax[e], __float_as_uint(fabsf(yy)));
        }
    }
    __syncthreads();
    if (t < 64) atomicMax(&g_amax[t], smax[t]);
}

// ============================================================
// kQ: quantize y' -> s8 hi/lo planes.  grid (64,8), block 256
// ============================================================
__global__ void __launch_bounds__(256) kQ() {
    const int e = blockIdx.x;
    const int j0 = ((blockIdx.y << 8) + threadIdx.x) << 2;
    const float s = __uint_as_float(g_amax[e]) * (1.f / 127.f);
    const float inv = (s > 0.f) ? 1.f / s : 0.f;
    float4 y = *(const float4*)(g_yf + (size_t)e * NN + j0);
    float qv[4] = { y.x * inv, y.y * inv, y.z * inv, y.w * inv };
    int hb = 0, lb = 0;
#pragma unroll
    for (int v = 0; v < 4; ++v) {
        float hq = rintf(qv[v]);
        hq = fminf(fmaxf(hq, -127.f), 127.f);
        float lq = rintf((qv[v] - hq) * 254.f);
        lq = fminf(fmaxf(lq, -127.f), 127.f);
        hb |= ((int)hq & 0xFF) << (8 * v);
        lb |= ((int)lq & 0xFF) << (8 * v);
    }
    *(int*)(g_ys + (size_t)e * NN + j0) = hb;
    *(int*)(g_ys + (size_t)(64 + e) * NN + j0) = lb;
}

// ============================================================
// kG2: C[64x128] = A_tile @ [h|l] in s8 (exact integer accumulation).
// 512 threads, warp-tile m16 x n32, K=128/iter (4 x k32 MMA).
// smem: mask 3x1KB @0, B 3x16KB @4096; epilogue aliases Csm @4096, psum @36864
// ============================================================
__global__ void __launch_bounds__(512) kG2(const float* __restrict__ b2,
                                           const float* __restrict__ cw,
                                           const float* __restrict__ cb,
                                           float* __restrict__ dout) {
    extern __shared__ __align__(16) char sm[];
    const uint32_t sb = s2u(sm);
    const int t = threadIdx.x, lane = t & 31, wid = t >> 5;
    const int g = lane >> 2, tq = lane & 3;
    const int wm = wid & 3, wn = wid >> 2;     // 4 m-tiles x 4 warps-in-n
    const int m0 = blockIdx.x << 6;

    const uint32_t MS = sb, BS = sb + 4096;
    // ldmatrix per-lane row bases (unswizzled; swizzle applied per-kk)
    uint32_t lmrow0, lmrow1;
    {
        const int ng = lane >> 3, rr = lane & 7;
        const int pair = ng >> 1, half = ng & 1;
        lmrow0 = (uint32_t)((wn * 32 + pair * 8 + rr) * 128 + half * 16);
        lmrow1 = lmrow0 + 16 * 128;
    }

    int acc[4][4];
#pragma unroll
    for (int b = 0; b < 4; ++b)
#pragma unroll
        for (int c = 0; c < 4; ++c) acc[b][c] = 0;

#pragma unroll
    for (int s = 0; s < 2; ++s) { ldch2(m0, s, MS + s * 1024, BS + s * 16384, t); CP_COMMIT(); }

    for (int dc = 0; dc < NDC; ++dc) {
        const int s = dc % 3;
        CP_WAIT(1);
        __syncthreads();
        if (dc + 2 < NDC)
            ldch2(m0, dc + 2, MS + ((dc + 2) % 3) * 1024, BS + ((dc + 2) % 3) * 16384, t);
        CP_COMMIT();
        const uint32_t mS = MS + s * 1024, bS = BS + s * 16384;
        uint4 mw  = lds128(mS + (wm * 16 + g) * 16);
        uint4 mw8 = lds128(mS + (wm * 16 + g + 8) * 16);
#pragma unroll
        for (int kk = 0; kk < 4; ++kk) {
            const uint32_t w  = (kk == 0) ? mw.x  : (kk == 1) ? mw.y  : (kk == 2) ? mw.z  : mw.w;
            const uint32_t w8 = (kk == 0) ? mw8.x : (kk == 1) ? mw8.y : (kk == 2) ? mw8.z : mw8.w;
            uint32_t a0 = exp4((w  >> (4 * tq)) & 15u);
            uint32_t a1 = exp4((w8 >> (4 * tq)) & 15u);
            uint32_t a2 = exp4((w  >> (16 + 4 * tq)) & 15u);
            uint32_t a3 = exp4((w8 >> (16 + 4 * tq)) & 15u);
            uint32_t b00, b01, b10, b11, b20, b21, b30, b31;
            ldmx4(b00, b01, b10, b11, bS + swz(lmrow0 + kk * 32));
            ldmx4(b20, b21, b30, b31, bS + swz(lmrow1 + kk * 32));
            mmas8(acc[0], a0, a1, a2, a3, b00, b01);
            mmas8(acc[1], a0, a1, a2, a3, b10, b11);
            mmas8(acc[2], a0, a1, a2, a3, b20, b21);
            mmas8(acc[3], a0, a1, a2, a3, b30, b31);
        }
    }
    CP_WAIT(0);
    __syncthreads();

    int* Csm = (int*)(sm + 4096);
#pragma unroll
    for (int bn = 0; bn < 4; ++bn) {
        const int row = wm * 16 + g;
        const int col = wn * 32 + bn * 8 + 2 * tq;
        Csm[row * 128 + col]           = acc[bn][0];
        Csm[row * 128 + col + 1]       = acc[bn][1];
        Csm[(row + 8) * 128 + col]     = acc[bn][2];
        Csm[(row + 8) * 128 + col + 1] = acc[bn][3];
    }
    float* psum = (float*)(sm + 36864);   // [8][64]
    __syncthreads();
    {
        const int r = t & 63, q = t >> 6;
        const float dinv = g_dinv[m0 + r];
        float p = 0.f;
#pragma unroll
        for (int v = 0; v < 8; ++v) {
            const int d = q * 8 + v;
            const float se = __uint_as_float(g_amax[d]) * (1.f / 127.f);
            const float ysum = se * ((float)Csm[r * 128 + d]
                                   + (float)Csm[r * 128 + 64 + d] * (1.f / 254.f));
            float hh = fmaxf(dinv * ysum + b2[d], 0.f);
            p += hh * cw[d];
        }
        psum[q * 64 + r] = p;
    }
    __syncthreads();
    if (t < 64) {
        float p = psum[t] + psum[64 + t] + psum[128 + t] + psum[192 + t]
                + psum[256 + t] + psum[320 + t] + psum[384 + t] + psum[448 + t];
        dout[m0 + t] = p + cb[0];
    }
}

// ============================================================
extern "C" void kernel_launch(void* const* d_in, const int* in_sizes, int n_in,
                              void* d_out, int out_size) {
    const float* states = (const float*)d_in[0];
    const float* W1 = (const float*)d_in[1];
    const float* b1 = (const float*)d_in[2];
    const float* W2 = (const float*)d_in[3];
    const float* b2 = (const float*)d_in[4];
    const float* cw = (const float*)d_in[5];
    const float* cb = (const float*)d_in[6];
    float* out = (float*)d_out;

    const int smemA  = NN * (int)sizeof(float2) + 64;
    const int smemG1 = 29184;
    const int smemG2 = 4096 + 3 * 16384;   // 53248

    cudaFuncSetAttribute(kA,  cudaFuncAttributeMaxDynamicSharedMemorySize, smemA);
    cudaFuncSetAttribute(kG1, cudaFuncAttributeMaxDynamicSharedMemorySize, smemG1);
    cudaFuncSetAttribute(kG2, cudaFuncAttributeMaxDynamicSharedMemorySize, smemG2);

    kA<<<512, 256, smemA>>>((const float4*)states, out + NN);
    kG1<<<128, 256, smemG1>>>(W1, b1, W2);
    kQ<<<dim3(64, 8), 256>>>();
    kG2<<<128, 512, smemG2>>>(b2, cw, cb, out);
}

// round 12
// speedup vs baseline: 1.5021x; 1.5021x over previous
#include <cuda_runtime.h>
#include <cuda_bf16.h>
#include <cuda_fp16.h>
#include <cstdint>
#include <cstddef>

#define NN   8192
#define NWRD 256
#define NDC  64     // double-chunks of K=128

__device__ unsigned      g_bits[NN * NWRD];  // 8 MB adjacency bitmask
__device__ float         g_dinv[NN];
__device__ __nv_bfloat16 g_sbt[8 * NN];      // rows 0-3: hi(dinv_j*s_j), 4-7: lo
__device__ __half        g_yh[64 * NN];      // fp16 y' = dinv_j*(h1@W2), [e][j]

// ---------------- helpers ----------------
__device__ __forceinline__ uint32_t s2u(const void* p) {
    uint32_t a;
    asm("{ .reg .u64 t; cvta.to.shared.u64 t, %1; cvt.u32.u64 %0, t; }" : "=r"(a) : "l"(p));
    return a;
}
__device__ __forceinline__ uint32_t swz(uint32_t b) { return b ^ ((b >> 3) & 0x70); }
__device__ __forceinline__ void cpa16(uint32_t s, const void* g) {
    asm volatile("cp.async.cg.shared.global [%0], [%1], 16;" :: "r"(s), "l"(g) : "memory");
}
#define CP_COMMIT() asm volatile("cp.async.commit_group;" ::: "memory")
#define CP_WAIT(n)  asm volatile("cp.async.wait_group %0;" :: "n"(n) : "memory")

__device__ __forceinline__ uint4 lds128(uint32_t a) {
    uint4 v;
    asm("ld.shared.v4.b32 {%0,%1,%2,%3}, [%4];"
        : "=r"(v.x), "=r"(v.y), "=r"(v.z), "=r"(v.w) : "r"(a));
    return v;
}
__device__ __forceinline__ void ldmx4(uint32_t& r0, uint32_t& r1, uint32_t& r2, uint32_t& r3,
                                      uint32_t a) {
    asm volatile("ldmatrix.sync.aligned.m8n8.x4.shared.b16 {%0,%1,%2,%3}, [%4];"
                 : "=r"(r0), "=r"(r1), "=r"(r2), "=r"(r3) : "r"(a));
}
__device__ __forceinline__ void ldmx2(uint32_t& r0, uint32_t& r1, uint32_t a) {
    asm volatile("ldmatrix.sync.aligned.m8n8.x2.shared.b16 {%0,%1}, [%2];"
                 : "=r"(r0), "=r"(r1) : "r"(a));
}
__device__ __forceinline__ uint32_t lutbf(uint32_t p) {      // bf16 {0|1,0|1}
    return ((p & 1u) ? 0x3F80u : 0u) | ((p & 2u) ? 0x3F800000u : 0u);
}
__device__ __forceinline__ uint32_t luth(uint32_t p) {       // fp16 {0|1,0|1}
    return ((p & 1u) ? 0x3C00u : 0u) | ((p & 2u) ? 0x3C000000u : 0u);
}
__device__ __forceinline__ void mma16816(float* c, uint32_t a0, uint32_t a1, uint32_t a2,
                                         uint32_t a3, uint32_t b0, uint32_t b1) {
    asm volatile("mma.sync.aligned.m16n8k16.row.col.f32.bf16.bf16.f32 "
                 "{%0,%1,%2,%3}, {%4,%5,%6,%7}, {%8,%9}, {%0,%1,%2,%3};"
                 : "+f"(c[0]), "+f"(c[1]), "+f"(c[2]), "+f"(c[3])
                 : "r"(a0), "r"(a1), "r"(a2), "r"(a3), "r"(b0), "r"(b1));
}
__device__ __forceinline__ void mmah16(float* c, uint32_t a0, uint32_t a1, uint32_t a2,
                                       uint32_t a3, uint32_t b0, uint32_t b1) {
    asm volatile("mma.sync.aligned.m16n8k16.row.col.f32.f16.f16.f32 "
                 "{%0,%1,%2,%3}, {%4,%5,%6,%7}, {%8,%9}, {%0,%1,%2,%3};"
                 : "+f"(c[0]), "+f"(c[1]), "+f"(c[2]), "+f"(c[3])
                 : "r"(a0), "r"(a1), "r"(a2), "r"(a3), "r"(b0), "r"(b1));
}
// decode 4 A regs (one kk step) from two 64-bit row-words — bf16 variant
__device__ __forceinline__ void decA(uint2 wg, uint2 wg8, int kk, int tq,
                                     uint32_t& a0, uint32_t& a1, uint32_t& a2, uint32_t& a3) {
    const uint32_t w0 = (kk < 2) ? wg.x : wg.y;
    const uint32_t w1 = (kk < 2) ? wg8.x : wg8.y;
    const int sh = ((kk & 1) << 4) + (tq << 1);
    a0 = lutbf((w0 >> sh) & 3u);
    a1 = lutbf((w1 >> sh) & 3u);
    a2 = lutbf((w0 >> (sh + 8)) & 3u);
    a3 = lutbf((w1 >> (sh + 8)) & 3u);
}
// fp16 variant
__device__ __forceinline__ void decAh(uint2 wg, uint2 wg8, int kk, int tq,
                                      uint32_t& a0, uint32_t& a1, uint32_t& a2, uint32_t& a3) {
    const uint32_t w0 = (kk < 2) ? wg.x : wg.y;
    const uint32_t w1 = (kk < 2) ? wg8.x : wg8.y;
    const int sh = ((kk & 1) << 4) + (tq << 1);
    a0 = luth((w0 >> sh) & 3u);
    a1 = luth((w1 >> sh) & 3u);
    a2 = luth((w0 >> (sh + 8)) & 3u);
    a3 = luth((w1 >> (sh + 8)) & 3u);
}

// ============================================================
// kA: distances -> f32 mask + bitmask + dinv + s' hi/lo; 4 rows per pos-load
// ============================================================
__global__ void __launch_bounds__(256) kA(const float4* __restrict__ st, float* __restrict__ omask) {
    extern __shared__ __align__(16) char smemA[];
    float2* spos = (float2*)smemA;
    int*    sdeg = (int*)(spos + NN);
    const int t = threadIdx.x, lane = t & 31;

    for (int j = t; j < NN; j += 256) { float4 s = st[j]; spos[j] = make_float2(s.x, s.y); }
    if (t < 16) sdeg[t] = 0;
    __syncthreads();

    const int row0 = blockIdx.x << 4;
    const float4* sp4 = (const float4*)spos;

    for (int rq = 0; rq < 4; ++rq) {
        const int ib = row0 + (rq << 2);
        float xr[4], yr[4];
#pragma unroll
        for (int q = 0; q < 4; ++q) { xr[q] = spos[ib + q].x; yr[q] = spos[ib + q].y; }
        int cnt[4] = {0, 0, 0, 0};
#pragma unroll
        for (int c = 0; c < 8; ++c) {
            const int j = (c << 10) + (t << 2);
            float4 p01 = sp4[j >> 1], p23 = sp4[(j >> 1) + 1];
#pragma unroll
            for (int q = 0; q < 4; ++q) {
                float dx0 = xr[q] - p01.x, dy0 = yr[q] - p01.y;
                float dx1 = xr[q] - p01.z, dy1 = yr[q] - p01.w;
                float dx2 = xr[q] - p23.x, dy2 = yr[q] - p23.y;
                float dx3 = xr[q] - p23.z, dy3 = yr[q] - p23.w;
                unsigned m0 = (dx0 * dx0 + dy0 * dy0 <= 1.0f);
                unsigned m1 = (dx1 * dx1 + dy1 * dy1 <= 1.0f);
                unsigned m2 = (dx2 * dx2 + dy2 * dy2 <= 1.0f);
                unsigned m3 = (dx3 * dx3 + dy3 * dy3 <= 1.0f);
                float4 mf = make_float4(m0 ? 1.f : 0.f, m1 ? 1.f : 0.f,
                                        m2 ? 1.f : 0.f, m3 ? 1.f : 0.f);
                *reinterpret_cast<float4*>(omask + (size_t)(ib + q) * NN + j) = mf;
                unsigned nib = m0 | (m1 << 1) | (m2 << 2) | (m3 << 3);
                cnt[q] += (int)(m0 + m1 + m2 + m3);
                unsigned v = nib << ((lane & 7) * 4);
                v |= __shfl_xor_sync(0xffffffffu, v, 1);
                v |= __shfl_xor_sync(0xffffffffu, v, 2);
                v |= __shfl_xor_sync(0xffffffffu, v, 4);
                if ((lane & 7) == 0) {
                    const int jb = (c << 10) + ((t >> 5) << 7);
                    g_bits[(ib + q) * NWRD + (jb >> 5) + (lane >> 3)] = v;
                }
            }
        }
#pragma unroll
        for (int q = 0; q < 4; ++q) {
#pragma unroll
            for (int o = 16; o; o >>= 1) cnt[q] += __shfl_xor_sync(0xffffffffu, cnt[q], o);
            if (lane == 0) atomicAdd(&sdeg[(rq << 2) + q], cnt[q]);
        }
    }
    __syncthreads();

    if (t < 16) {
        const int i = row0 + t;
        const float dinv = rsqrtf((float)sdeg[t]);
        g_dinv[i] = dinv;
        float4 s = st[i];
        float v[4] = { dinv * s.x, dinv * s.y, dinv * s.z, dinv * s.w };
#pragma unroll
        for (int d = 0; d < 4; ++d) {
            __nv_bfloat16 hi = __float2bfloat16(v[d]);
            g_sbt[d * NN + i] = hi;
            g_sbt[(4 + d) * NN + i] = __float2bfloat16(v[d] - __bfloat162float(hi));
        }
    }
}

// ---------------- chunk loaders ----------------
// kG1 (256 thr): mask 1KB + B 2KB (bf16)
__device__ __forceinline__ void ldch1(int m0, int dc, uint32_t sM, uint32_t sB, int t) {
    if (t < 128) {
        int sub = t >> 6, rem = t & 63, row = rem >> 3, seg = rem & 7;
        cpa16(sB + sub * 1024 + swz(row * 128 + seg * 16),
              g_sbt + (size_t)row * NN + dc * 128 + sub * 64 + seg * 8);
    } else if (t < 192) {
        int row = t - 128;
        cpa16(sM + row * 16, g_bits + (size_t)(m0 + row) * NWRD + dc * 4);
    }
}
// kG2 (512 thr): mask 1KB + B 16KB (fp16, 64 rows, 2 sub-tiles of 128B rows)
__device__ __forceinline__ void ldch2(int m0, int dc, uint32_t sM, uint32_t sB, int t) {
    if (t < 64) cpa16(sM + t * 16, g_bits + (size_t)(m0 + t) * NWRD + dc * 4);
#pragma unroll
    for (int p = 0; p < 2; ++p) {
        int q = t + (p << 9);
        int sub = q >> 9, rem = q & 511, row = rem >> 3, seg = rem & 7;
        cpa16(sB + sub * 8192 + swz(row * 128 + seg * 16),
              g_yh + (size_t)row * NN + dc * 128 + sub * 64 + seg * 8);
    }
}

// ============================================================
// kG1: C[64x8] = A_tile @ [s'hi|s'lo]; split-K across warp halves; fused MLP.
// epilogue emits single fp16 plane g_yh.
// smem: mask 3x1KB @0, B 3x2KB @3072, w1 @9216, b1 @10240, w2 @10496, agg @26880
// ============================================================
__global__ void __launch_bounds__(256) kG1(const float* __restrict__ W1,
                                           const float* __restrict__ b1,
                                           const float* __restrict__ W2) {
    extern __shared__ __align__(16) char sm[];
    const uint32_t sb = s2u(sm);
    const int t = threadIdx.x, lane = t & 31, wid = t >> 5;
    const int g = lane >> 2, tq = lane & 3;
    const int h = wid >> 2, wr = wid & 3;
    const int m0 = blockIdx.x << 6;

    float* w1s = (float*)(sm + 9216);
    float* b1s = (float*)(sm + 10240);
    float* w2s = (float*)(sm + 10496);
    float* agg = (float*)(sm + 26880);   // [2][64][4]

    if (t < 256) w1s[t] = W1[t];
    if (t < 64)  b1s[t] = b1[t];
    for (int k = t; k < 4096; k += 256) w2s[k] = W2[k];

    const uint32_t MS = sb, BS = sb + 3072;
    const uint32_t lmbase = (lane & 7) * 128 + ((lane >> 3) & 1) * 16;

    float acc[4] = {0.f, 0.f, 0.f, 0.f};

#pragma unroll
    for (int s = 0; s < 2; ++s) { ldch1(m0, s, MS + s * 1024, BS + s * 2048, t); CP_COMMIT(); }

    for (int dc = 0; dc < NDC; ++dc) {
        const int s = dc % 3;
        CP_WAIT(1);
        __syncthreads();
        if (dc + 2 < NDC)
            ldch1(m0, dc + 2, MS + ((dc + 2) % 3) * 1024, BS + ((dc + 2) % 3) * 2048, t);
        CP_COMMIT();
        const uint32_t mS = MS + s * 1024;
        const uint32_t bsub = BS + s * 2048 + h * 1024;
        uint4 w0 = lds128(mS + (wr * 16 + g) * 16);
        uint4 w8 = lds128(mS + (wr * 16 + g + 8) * 16);
        uint2 wg  = h ? make_uint2(w0.z, w0.w) : make_uint2(w0.x, w0.y);
        uint2 wg8 = h ? make_uint2(w8.z, w8.w) : make_uint2(w8.x, w8.y);
#pragma unroll
        for (int kk = 0; kk < 4; ++kk) {
            uint32_t a0, a1, a2, a3, b0, b1r;
            decA(wg, wg8, kk, tq, a0, a1, a2, a3);
            ldmx2(b0, b1r, bsub + swz(lmbase + kk * 32));
            mma16816(acc, a0, a1, a2, a3, b0, b1r);
        }
    }
    CP_WAIT(0);

    {
        float s0 = acc[0] + __shfl_xor_sync(0xffffffffu, acc[0], 2);
        float s1 = acc[1] + __shfl_xor_sync(0xffffffffu, acc[1], 2);
        float s2 = acc[2] + __shfl_xor_sync(0xffffffffu, acc[2], 2);
        float s3 = acc[3] + __shfl_xor_sync(0xffffffffu, acc[3], 2);
        if (tq < 2) {
            const int row = wr * 16 + g;
            float* ag = agg + h * 256;
            ag[row * 4 + 2 * tq] = s0;
            ag[row * 4 + 2 * tq + 1] = s1;
            ag[(row + 8) * 4 + 2 * tq] = s2;
            ag[(row + 8) * 4 + 2 * tq + 1] = s3;
        }
    }
    __syncthreads();

    {
        const int r = t & 63, q = t >> 6, i = m0 + r;
        const float dinv = g_dinv[i];
        const float a0 = dinv * (agg[r * 4 + 0] + agg[256 + r * 4 + 0]);
        const float a1 = dinv * (agg[r * 4 + 1] + agg[256 + r * 4 + 1]);
        const float a2 = dinv * (agg[r * 4 + 2] + agg[256 + r * 4 + 2]);
        const float a3 = dinv * (agg[r * 4 + 3] + agg[256 + r * 4 + 3]);
        float hh[64];
#pragma unroll
        for (int k = 0; k < 64; ++k)
            hh[k] = fmaxf(b1s[k] + a0 * w1s[k] + a1 * w1s[64 + k]
                        + a2 * w1s[128 + k] + a3 * w1s[192 + k], 0.f);
        float y[16];
#pragma unroll
        for (int v = 0; v < 16; ++v) y[v] = 0.f;
        for (int k = 0; k < 64; ++k) {
            const float hk = hh[k];
            const float4* w4 = (const float4*)(w2s + k * 64 + q * 16);
#pragma unroll
            for (int v = 0; v < 4; ++v) {
                float4 w = w4[v];
                y[4 * v + 0] += hk * w.x;
                y[4 * v + 1] += hk * w.y;
                y[4 * v + 2] += hk * w.z;
                y[4 * v + 3] += hk * w.w;
            }
        }
#pragma unroll
        for (int v = 0; v < 16; ++v) {
            const int e = q * 16 + v;
            g_yh[e * NN + i] = __float2half(dinv * y[v]);
        }
    }
}

// ============================================================
// kG2: C[64x64] = A_tile @ y'(fp16); 512 threads, warp-tile m16 x n16.
// smem: mask 3x1KB @0, B 3x16KB @4096; epilogue aliases Csm @4096, psum @20480
// ============================================================
__global__ void __launch_bounds__(512) kG2(const float* __restrict__ b2,
                                           const float* __restrict__ cw,
                                           const float* __restrict__ cb,
                                           float* __restrict__ dout) {
    extern __shared__ __align__(16) char sm[];
    const uint32_t sb = s2u(sm);
    const int t = threadIdx.x, lane = t & 31, wid = t >> 5;
    const int g = lane >> 2, tq = lane & 3;
    const int wm = wid & 3, wn = wid >> 2;     // 4 m16-tiles x 4 n16-groups
    const int m0 = blockIdx.x << 6;

    const uint32_t MS = sb, BS = sb + 4096;
    uint32_t lmbase;
    {
        const int rsel = ((lane >> 4) & 1) * 8 + (lane & 7);
        const int kb16 = ((lane >> 3) & 1) * 16;
        lmbase = (uint32_t)((wn * 16 + rsel) * 128 + kb16);
    }

    float acc[2][4];
#pragma unroll
    for (int b = 0; b < 2; ++b)
#pragma unroll
        for (int c = 0; c < 4; ++c) acc[b][c] = 0.f;

#pragma unroll
    for (int s = 0; s < 2; ++s) { ldch2(m0, s, MS + s * 1024, BS + s * 16384, t); CP_COMMIT(); }

    for (int dc = 0; dc < NDC; ++dc) {
        const int s = dc % 3;
        CP_WAIT(1);
        __syncthreads();
        if (dc + 2 < NDC)
            ldch2(m0, dc + 2, MS + ((dc + 2) % 3) * 1024, BS + ((dc + 2) % 3) * 16384, t);
        CP_COMMIT();
        const uint32_t mS = MS + s * 1024, bS = BS + s * 16384;
        uint4 mw  = lds128(mS + (wm * 16 + g) * 16);
        uint4 mw8 = lds128(mS + (wm * 16 + g + 8) * 16);
#pragma unroll
        for (int sub = 0; sub < 2; ++sub) {
            const uint32_t bsub = bS + sub * 8192;
            uint2 wg  = sub ? make_uint2(mw.z, mw.w) : make_uint2(mw.x, mw.y);
            uint2 wg8 = sub ? make_uint2(mw8.z, mw8.w) : make_uint2(mw8.x, mw8.y);
#pragma unroll
            for (int kk = 0; kk < 4; ++kk) {
                uint32_t a0, a1, a2, a3, b00, b01, b10, b11;
                decAh(wg, wg8, kk, tq, a0, a1, a2, a3);
                ldmx4(b00, b01, b10, b11, bsub + swz(lmbase + kk * 32));
                mmah16(acc[0], a0, a1, a2, a3, b00, b01);
                mmah16(acc[1], a0, a1, a2, a3, b10, b11);
            }
        }
    }
    CP_WAIT(0);
    __syncthreads();

    float* Csm = (float*)(sm + 4096);   // [64][64] f32
#pragma unroll
    for (int bn = 0; bn < 2; ++bn) {
        const int row = wm * 16 + g;
        const int col = wn * 16 + bn * 8 + 2 * tq;
        Csm[row * 64 + col]           = acc[bn][0];
        Csm[row * 64 + col + 1]       = acc[bn][1];
        Csm[(row + 8) * 64 + col]     = acc[bn][2];
        Csm[(row + 8) * 64 + col + 1] = acc[bn][3];
    }
    float* psum = (float*)(sm + 20480);   // [8][64]
    __syncthreads();
    {
        const int r = t & 63, q = t >> 6;
        const float dinv = g_dinv[m0 + r];
        float p = 0.f;
#pragma unroll
        for (int v = 0; v < 8; ++v) {
            const int d = q * 8 + v;
            float hh = fmaxf(dinv * Csm[r * 64 + d] + b2[d], 0.f);
            p += hh * cw[d];
        }
        psum[q * 64 + r] = p;
    }
    __syncthreads();
    if (t < 64) {
        float p = psum[t] + psum[64 + t] + psum[128 + t] + psum[192 + t]
                + psum[256 + t] + psum[320 + t] + psum[384 + t] + psum[448 + t];
        dout[m0 + t] = p + cb[0];
    }
}

// ============================================================
extern "C" void kernel_launch(void* const* d_in, const int* in_sizes, int n_in,
                              void* d_out, int out_size) {
    const float* states = (const float*)d_in[0];
    const float* W1 = (const float*)d_in[1];
    const float* b1 = (const float*)d_in[2];
    const float* W2 = (const float*)d_in[3];
    const float* b2 = (const float*)d_in[4];
    const float* cw = (const float*)d_in[5];
    const float* cb = (const float*)d_in[6];
    float* out = (float*)d_out;

    const int smemA  = NN * (int)sizeof(float2) + 64;
    const int smemG1 = 28928;
    const int smemG2 = 4096 + 3 * 16384;   // 53248

    cudaFuncSetAttribute(kA,  cudaFuncAttributeMaxDynamicSharedMemorySize, smemA);
    cudaFuncSetAttribute(kG1, cudaFuncAttributeMaxDynamicSharedMemorySize, smemG1);
    cudaFuncSetAttribute(kG2, cudaFuncAttributeMaxDynamicSharedMemorySize, smemG2);

    kA<<<512, 256, smemA>>>((const float4*)states, out + NN);
    kG1<<<128, 256, smemG1>>>(W1, b1, W2);
    kG2<<<128, 512, smemG2>>>(b2, cw, cb, out);
}